// round 14
// baseline (speedup 1.0000x reference)
#include <cuda_runtime.h>

#define NMAX 100000
#define EMAX 1600000
#define NG 64
#define NH 64

// ---- scratch (static device globals; no allocations allowed) ----
__device__ __align__(16) float g_h[(size_t)NMAX * NH];
__device__ __align__(16) float g_agg[(size_t)NMAX * NH];   // gemm-init'd, scatter-accumulated
__device__ float g_dinv[NMAX];
__device__ float g_selfw[NMAX];          // 1/deg (= dinv^2)
__device__ int   g_cnt[NMAX];
__device__ int   g_rowptr[NMAX + 1];
__device__ int   g_cursor[NMAX];
__device__ __align__(8) int2 g_edge[EMAX];   // sorted by dst: .x = src, .y = norm bits
__device__ int   g_dsts[EMAX];               // sorted dst per edge
__device__ float g_pooled[NG * NH];

// ---------------- CSR build: histogram -> scan -> place ----------------

__global__ void k_zero_cnt(int n) {
    int i = blockIdx.x * blockDim.x + threadIdx.x;
    if (i < n) g_cnt[i] = 0;
}

__global__ void k_count(const int* __restrict__ ei, int E, int n) {
    int e = blockIdx.x * blockDim.x + threadIdx.x;
    if (e < E) {
        int d = ei[(size_t)E + e];
        d = d < 0 ? 0 : (d >= n ? n - 1 : d);
        atomicAdd(&g_cnt[d], 1);
    }
}

__global__ void __launch_bounds__(1024) k_scan(int n, int E) {
    __shared__ int ssum[1024];
    const int tid = threadIdx.x;
    const int per = (n + 1023) / 1024;
    const int start = tid * per;
    const int end   = min(start + per, n);

    int s = 0;
    for (int i = start; i < end; i++) s += g_cnt[i];
    ssum[tid] = s;
    __syncthreads();

    for (int d = 1; d < 1024; d <<= 1) {
        int v = (tid >= d) ? ssum[tid - d] : 0;
        __syncthreads();
        ssum[tid] += v;
        __syncthreads();
    }
    int off = ssum[tid] - s;

    for (int i = start; i < end; i++) {
        int c = g_cnt[i];
        g_rowptr[i] = off;
        g_cursor[i] = off;
        float deg = (float)(c + 1);          // self-loop included
        g_dinv[i]  = rsqrtf(deg);
        g_selfw[i] = 1.0f / deg;
        off += c;
    }
    if (tid == 1023) g_rowptr[n] = E;
}

__global__ void __launch_bounds__(256) k_place(const int* __restrict__ ei, int E, int n) {
    int i = blockIdx.x * blockDim.x + threadIdx.x;
    int Eh = (E + 1) / 2;
    if (i >= Eh) return;
    int e0 = i, e1 = i + Eh;
    bool has1 = e1 < E;

    int s0 = ei[e0];
    int d0 = ei[(size_t)E + e0];
    int s1 = has1 ? ei[e1] : 0;
    int d1 = has1 ? ei[(size_t)E + e1] : 0;

    s0 = s0 < 0 ? 0 : (s0 >= n ? n - 1 : s0);
    d0 = d0 < 0 ? 0 : (d0 >= n ? n - 1 : d0);
    s1 = s1 < 0 ? 0 : (s1 >= n ? n - 1 : s1);
    d1 = d1 < 0 ? 0 : (d1 >= n ? n - 1 : d1);

    int p0 = atomicAdd(&g_cursor[d0], 1);
    int p1 = has1 ? atomicAdd(&g_cursor[d1], 1) : 0;

    g_edge[p0] = make_int2(s0, __float_as_int(g_dinv[s0] * g_dinv[d0]));
    g_dsts[p0] = d0;
    if (has1) {
        g_edge[p1] = make_int2(s1, __float_as_int(g_dinv[s1] * g_dinv[d1]));
        g_dsts[p1] = d1;
    }
}

// ---- GEMM: H = X @ W; also initializes agg = H*selfw + bias (self-loop+bias) ----
// RELU_IN: apply relu when reading X (X = g_agg of the previous layer).
// In-place g_agg read->write is safe: each block reads exactly the rows it
// writes, and a __syncthreads() separates the last tile read from the epilogue.

template<int K, bool RELU_IN>
__global__ void __launch_bounds__(256) k_gemm(const float* __restrict__ Xin,
                                              const float* __restrict__ W,
                                              const float* __restrict__ bias, int n) {
    __shared__ float Ws[64 * 64];
    __shared__ float Xs[64 * 68];

    const float* __restrict__ X = RELU_IN ? (const float*)g_agg : Xin;
    const int tid  = threadIdx.x;
    const int row0 = blockIdx.x * 64;
    const int r = (tid >> 4) << 2;
    const int c = (tid & 15) << 2;

    float acc[4][4] = {};

    for (int kc = 0; kc < K; kc += 64) {
        for (int i = tid; i < 64 * 16; i += 256)
            ((float4*)Ws)[i] = ((const float4*)(W + (size_t)kc * 64))[i];
        for (int i = tid; i < 64 * 16; i += 256) {
            int rr = i >> 4, c4 = i & 15;
            float4 v = make_float4(0.f, 0.f, 0.f, 0.f);
            if (row0 + rr < n) {
                v = *((const float4*)(X + (size_t)(row0 + rr) * K + kc + c4 * 4));
                if (RELU_IN) {
                    v.x = fmaxf(v.x, 0.f); v.y = fmaxf(v.y, 0.f);
                    v.z = fmaxf(v.z, 0.f); v.w = fmaxf(v.w, 0.f);
                }
            }
            *((float4*)(Xs + rr * 68 + c4 * 4)) = v;
        }
        __syncthreads();

        #pragma unroll 16
        for (int k = 0; k < 64; k++) {
            float4 wb = *((const float4*)(Ws + k * 64 + c));
            float a0 = Xs[(r + 0) * 68 + k];
            float a1 = Xs[(r + 1) * 68 + k];
            float a2 = Xs[(r + 2) * 68 + k];
            float a3 = Xs[(r + 3) * 68 + k];
            acc[0][0] += a0 * wb.x; acc[0][1] += a0 * wb.y; acc[0][2] += a0 * wb.z; acc[0][3] += a0 * wb.w;
            acc[1][0] += a1 * wb.x; acc[1][1] += a1 * wb.y; acc[1][2] += a1 * wb.z; acc[1][3] += a1 * wb.w;
            acc[2][0] += a2 * wb.x; acc[2][1] += a2 * wb.y; acc[2][2] += a2 * wb.z; acc[2][3] += a2 * wb.w;
            acc[3][0] += a3 * wb.x; acc[3][1] += a3 * wb.y; acc[3][2] += a3 * wb.z; acc[3][3] += a3 * wb.w;
        }
        __syncthreads();
    }

    float bc0 = bias[c + 0], bc1 = bias[c + 1], bc2 = bias[c + 2], bc3 = bias[c + 3];

    #pragma unroll
    for (int i = 0; i < 4; i++) {
        int rr = row0 + r + i;
        if (rr < n) {
            float4 h4 = make_float4(acc[i][0], acc[i][1], acc[i][2], acc[i][3]);
            *((float4*)(g_h + (size_t)rr * 64 + c)) = h4;
            float sw = g_selfw[rr];
            float4 a4;
            a4.x = fmaf(h4.x, sw, bc0); a4.y = fmaf(h4.y, sw, bc1);
            a4.z = fmaf(h4.z, sw, bc2); a4.w = fmaf(h4.w, sw, bc3);
            *((float4*)(g_agg + (size_t)rr * 64 + c)) = a4;
        }
    }
}

// ---- segmented scatter on dst-sorted edges ----
// Block = 16 lane-groups x 16 edges (consecutive in CSR order). Gather
// h[src]*norm into smem; only run-head groups emit ONE red.global.add.v4
// per lane for their whole same-dst run (~2 atomics/block at mean degree 16).

__global__ void __launch_bounds__(256) k_scatter_seg(int E) {
    __shared__ float4 sval[16][17];   // [group][lane], padded
    __shared__ int sdst[16];

    const int g = threadIdx.x >> 4;
    const int l = threadIdx.x & 15;
    const int e = blockIdx.x * 16 + g;

    int dst = -1;
    float4 val = make_float4(0.f, 0.f, 0.f, 0.f);
    if (e < E) {
        int2 p = g_edge[e];
        dst = g_dsts[e];
        float nrm = __int_as_float(p.y);
        float4 v = *((const float4*)(g_h + (size_t)p.x * 64 + l * 4));
        val.x = v.x * nrm; val.y = v.y * nrm; val.z = v.z * nrm; val.w = v.w * nrm;
    }
    if (l == 0) sdst[g] = dst;
    sval[g][l] = val;
    __syncthreads();

    int myd = sdst[g];
    bool head = (myd >= 0) && (g == 0 || sdst[g - 1] != myd);
    if (head) {
        float4 acc = sval[g][l];
        int r = g + 1;
        while (r < 16 && sdst[r] == myd) {
            float4 t = sval[r][l];
            acc.x += t.x; acc.y += t.y; acc.z += t.z; acc.w += t.w;
            r++;
        }
        float* p = g_agg + (size_t)myd * 64 + l * 4;
        asm volatile("red.global.add.v4.f32 [%0], {%1, %2, %3, %4};"
                     :: "l"(p), "f"(acc.x), "f"(acc.y), "f"(acc.z), "f"(acc.w)
                     : "memory");
    }
}

// ---------------- mean-pool per graph (reads relu(g_agg); batch sorted) ----------------

__device__ __forceinline__ int lower_bound_i(const int* b, int n, int v) {
    int lo = 0, hi = n;
    while (lo < hi) {
        int m = (lo + hi) >> 1;
        if (b[m] < v) lo = m + 1; else hi = m;
    }
    return lo;
}

__global__ void k_pool(const int* __restrict__ batch, int n) {
    __shared__ int s_bounds[2];
    __shared__ float red[256];
    int g = blockIdx.x;
    if (threadIdx.x == 0) {
        s_bounds[0] = lower_bound_i(batch, n, g);
        s_bounds[1] = lower_bound_i(batch, n, g + 1);
    }
    __syncthreads();
    int start = s_bounds[0], end = s_bounds[1];
    int f = threadIdx.x & 63, j = threadIdx.x >> 6;
    float acc = 0.f;
    for (int node = start + j; node < end; node += 4)
        acc += fmaxf(g_agg[(size_t)node * 64 + f], 0.f);
    red[threadIdx.x] = acc;
    __syncthreads();
    if (j == 0) {
        float s = red[f] + red[64 + f] + red[128 + f] + red[192 + f];
        float cnt = (float)(end - start);
        g_pooled[g * 64 + f] = s / fmaxf(cnt, 1.0f);
    }
}

// ---------------- final linear + softmax ----------------

__global__ void k_final(const float* __restrict__ Wl, const float* __restrict__ bl,
                        float* __restrict__ out) {
    int g = threadIdx.x;
    if (g >= NG) return;
    float p[64];
    #pragma unroll
    for (int f = 0; f < 64; f++) p[f] = g_pooled[g * 64 + f];
    float logits[10];
    #pragma unroll
    for (int c = 0; c < 10; c++) {
        float s = bl[c];
        #pragma unroll
        for (int f = 0; f < 64; f++) s += p[f] * Wl[f * 10 + c];
        logits[c] = s;
    }
    float m = logits[0];
    #pragma unroll
    for (int c = 1; c < 10; c++) m = fmaxf(m, logits[c]);
    float sum = 0.f;
    #pragma unroll
    for (int c = 0; c < 10; c++) { logits[c] = expf(logits[c] - m); sum += logits[c]; }
    float inv = 1.0f / sum;
    #pragma unroll
    for (int c = 0; c < 10; c++) out[g * 10 + c] = logits[c] * inv;
}

// ---------------- launch ----------------
// Inputs bound BY ELEMENT COUNT. edge_index/batch are int32 (JAX x64-disabled).

extern "C" void kernel_launch(void* const* d_in, const int* in_sizes, int n_in,
                              void* d_out, int out_size) {
    (void)out_size;
    const float* x = nullptr;
    const int* ei = nullptr;
    const int* batch = nullptr;
    const float *W1 = nullptr, *W2 = nullptr, *W3 = nullptr, *Wl = nullptr;
    const float *b1 = nullptr, *b2 = nullptr, *b3 = nullptr, *bl = nullptr;
    int ei_elems = 0, batch_elems = 0;
    int n4096 = 0, n64 = 0;

    for (int i = 0; i < n_in; i++) {
        int sz = in_sizes[i];
        const void* p = d_in[i];
        if (sz == 100000 * 128)      x = (const float*)p;
        else if (sz == 2 * 1600000)  { ei = (const int*)p; ei_elems = sz; }
        else if (sz == 100000)       { batch = (const int*)p; batch_elems = sz; }
        else if (sz == 128 * 64)     W1 = (const float*)p;
        else if (sz == 64 * 64)      { if (n4096++ == 0) W2 = (const float*)p; else W3 = (const float*)p; }
        else if (sz == 64)           { if (n64 == 0) b1 = (const float*)p;
                                       else if (n64 == 1) b2 = (const float*)p;
                                       else b3 = (const float*)p; n64++; }
        else if (sz == 64 * 10)      Wl = (const float*)p;
        else if (sz == 10)           bl = (const float*)p;
    }
    if (!x || !ei || !batch || !W1 || !W2 || !W3 || !b1 || !b2 || !b3 || !Wl || !bl)
        return;

    int n = batch_elems;     if (n > NMAX) n = NMAX;
    int E = ei_elems / 2;    if (E > EMAX) E = EMAX;

    const int TB = 256;
    const int nbN  = (n + TB - 1) / TB;
    const int nbE  = (E + TB - 1) / TB;
    const int nbEh = ((E + 1) / 2 + TB - 1) / TB;
    const int nbGm = (n + 63) / 64;
    const int nbSc = (E + 15) / 16;

    // CSR build (dst-sorted edges) + norms
    k_zero_cnt<<<nbN, TB>>>(n);
    k_count<<<nbE, TB>>>(ei, E, n);
    k_scan<<<1, 1024>>>(n, E);
    k_place<<<nbEh, TB>>>(ei, E, n);

    // layer 1 (K=128, input = x)
    k_gemm<128, false><<<nbGm, TB>>>(x, W1, b1, n);
    k_scatter_seg<<<nbSc, TB>>>(E);

    // layer 2 (reads relu(g_agg) in-place)
    k_gemm<64, true><<<nbGm, TB>>>(nullptr, W2, b2, n);
    k_scatter_seg<<<nbSc, TB>>>(E);

    // layer 3
    k_gemm<64, true><<<nbGm, TB>>>(nullptr, W3, b3, n);
    k_scatter_seg<<<nbSc, TB>>>(E);

    // pool + classify
    k_pool<<<NG, TB>>>(batch, n);
    k_final<<<1, 64>>>(Wl, bl, (float*)d_out);
}

// round 15
// speedup vs baseline: 1.8431x; 1.8431x over previous
#include <cuda_runtime.h>

#define NMAX 100000
#define EMAX 1600000
#define NG 64
#define NH 64

// ---- scratch (static device globals; no allocations allowed) ----
__device__ __align__(16) float g_h[(size_t)NMAX * NH];
__device__ __align__(16) float g_agg[(size_t)NMAX * NH];   // gemm-init'd: h*selfw + bias
__device__ float g_deg[NMAX];
__device__ float g_dinv[NMAX];
__device__ float g_selfw[NMAX];
__device__ int   g_src[EMAX];
__device__ int   g_dst[EMAX];
__device__ float g_norm[EMAX];
__device__ float g_pooled[NG * NH];

// ---------------- degree / norm prep (R5-proven) ----------------

__global__ void k_init_deg(int n) {
    int i = blockIdx.x * blockDim.x + threadIdx.x;
    if (i < n) g_deg[i] = 1.0f;   // self-loop contributes 1
}

__global__ void k_prep_edges(const int* __restrict__ ei, int E, int n) {
    int e = blockIdx.x * blockDim.x + threadIdx.x;
    if (e < E) {
        int s = ei[e];
        int d = ei[(size_t)E + e];
        s = s < 0 ? 0 : (s >= n ? n - 1 : s);
        d = d < 0 ? 0 : (d >= n ? n - 1 : d);
        g_src[e] = s;
        g_dst[e] = d;
        atomicAdd(&g_deg[d], 1.0f);
    }
}

__global__ void k_dinv(int n) {
    int i = blockIdx.x * blockDim.x + threadIdx.x;
    if (i < n) {
        float deg = g_deg[i];
        g_dinv[i]  = rsqrtf(deg);
        g_selfw[i] = 1.0f / deg;
    }
}

__global__ void k_norm(int E) {
    int e = blockIdx.x * blockDim.x + threadIdx.x;
    if (e < E) g_norm[e] = g_dinv[g_src[e]] * g_dinv[g_dst[e]];
}

// ---- GEMM: H = X @ W; epilogue also writes agg = H*selfw + bias ----
// RELU_IN: X = relu(g_agg) of the previous layer (in-place safe: each block
// reads exactly the rows it writes; __syncthreads separates read from write).

template<int K, bool RELU_IN>
__global__ void __launch_bounds__(256) k_gemm(const float* __restrict__ Xin,
                                              const float* __restrict__ W,
                                              const float* __restrict__ bias, int n) {
    __shared__ float Ws[64 * 64];
    __shared__ float Xs[64 * 68];

    const float* __restrict__ X = RELU_IN ? (const float*)g_agg : Xin;
    const int tid  = threadIdx.x;
    const int row0 = blockIdx.x * 64;
    const int r = (tid >> 4) << 2;
    const int c = (tid & 15) << 2;

    float acc[4][4] = {};

    for (int kc = 0; kc < K; kc += 64) {
        for (int i = tid; i < 64 * 16; i += 256)
            ((float4*)Ws)[i] = ((const float4*)(W + (size_t)kc * 64))[i];
        for (int i = tid; i < 64 * 16; i += 256) {
            int rr = i >> 4, c4 = i & 15;
            float4 v = make_float4(0.f, 0.f, 0.f, 0.f);
            if (row0 + rr < n) {
                v = *((const float4*)(X + (size_t)(row0 + rr) * K + kc + c4 * 4));
                if (RELU_IN) {
                    v.x = fmaxf(v.x, 0.f); v.y = fmaxf(v.y, 0.f);
                    v.z = fmaxf(v.z, 0.f); v.w = fmaxf(v.w, 0.f);
                }
            }
            *((float4*)(Xs + rr * 68 + c4 * 4)) = v;
        }
        __syncthreads();

        #pragma unroll 16
        for (int k = 0; k < 64; k++) {
            float4 wb = *((const float4*)(Ws + k * 64 + c));
            float a0 = Xs[(r + 0) * 68 + k];
            float a1 = Xs[(r + 1) * 68 + k];
            float a2 = Xs[(r + 2) * 68 + k];
            float a3 = Xs[(r + 3) * 68 + k];
            acc[0][0] += a0 * wb.x; acc[0][1] += a0 * wb.y; acc[0][2] += a0 * wb.z; acc[0][3] += a0 * wb.w;
            acc[1][0] += a1 * wb.x; acc[1][1] += a1 * wb.y; acc[1][2] += a1 * wb.z; acc[1][3] += a1 * wb.w;
            acc[2][0] += a2 * wb.x; acc[2][1] += a2 * wb.y; acc[2][2] += a2 * wb.z; acc[2][3] += a2 * wb.w;
            acc[3][0] += a3 * wb.x; acc[3][1] += a3 * wb.y; acc[3][2] += a3 * wb.z; acc[3][3] += a3 * wb.w;
        }
        __syncthreads();
    }

    float bc0 = bias[c + 0], bc1 = bias[c + 1], bc2 = bias[c + 2], bc3 = bias[c + 3];

    #pragma unroll
    for (int i = 0; i < 4; i++) {
        int rr = row0 + r + i;
        if (rr < n) {
            float4 h4 = make_float4(acc[i][0], acc[i][1], acc[i][2], acc[i][3]);
            *((float4*)(g_h + (size_t)rr * 64 + c)) = h4;
            float sw = g_selfw[rr];
            float4 a4;
            a4.x = fmaf(h4.x, sw, bc0); a4.y = fmaf(h4.y, sw, bc1);
            a4.z = fmaf(h4.z, sw, bc2); a4.w = fmaf(h4.w, sw, bc3);
            *((float4*)(g_agg + (size_t)rr * 64 + c)) = a4;
        }
    }
}

// ---- edge scatter (R5-proven shape): agg[dst] += h[src]*norm ----
// 16 lanes per edge, one float4 per lane, 16B vector red.global.

__global__ void __launch_bounds__(256) k_scatter(int E) {
    int gid = blockIdx.x * blockDim.x + threadIdx.x;
    int e = gid >> 4;
    if (e >= E) return;
    int l = gid & 15;
    int s = g_src[e];
    int d = g_dst[e];
    float nrm = g_norm[e];
    float4 v = *((const float4*)(g_h + (size_t)s * 64 + l * 4));
    float* p = g_agg + (size_t)d * 64 + l * 4;
    asm volatile("red.global.add.v4.f32 [%0], {%1, %2, %3, %4};"
                 :: "l"(p), "f"(v.x * nrm), "f"(v.y * nrm), "f"(v.z * nrm), "f"(v.w * nrm)
                 : "memory");
}

// ---------------- mean-pool per graph (reads relu(g_agg); batch sorted) ----------------

__device__ __forceinline__ int lower_bound_i(const int* b, int n, int v) {
    int lo = 0, hi = n;
    while (lo < hi) {
        int m = (lo + hi) >> 1;
        if (b[m] < v) lo = m + 1; else hi = m;
    }
    return lo;
}

__global__ void k_pool(const int* __restrict__ batch, int n) {
    __shared__ int s_bounds[2];
    __shared__ float red[256];
    int g = blockIdx.x;
    if (threadIdx.x == 0) {
        s_bounds[0] = lower_bound_i(batch, n, g);
        s_bounds[1] = lower_bound_i(batch, n, g + 1);
    }
    __syncthreads();
    int start = s_bounds[0], end = s_bounds[1];
    int f = threadIdx.x & 63, j = threadIdx.x >> 6;
    float acc = 0.f;
    for (int node = start + j; node < end; node += 4)
        acc += fmaxf(g_agg[(size_t)node * 64 + f], 0.f);
    red[threadIdx.x] = acc;
    __syncthreads();
    if (j == 0) {
        float s = red[f] + red[64 + f] + red[128 + f] + red[192 + f];
        float cnt = (float)(end - start);
        g_pooled[g * 64 + f] = s / fmaxf(cnt, 1.0f);
    }
}

// ---------------- final linear + softmax ----------------

__global__ void k_final(const float* __restrict__ Wl, const float* __restrict__ bl,
                        float* __restrict__ out) {
    int g = threadIdx.x;
    if (g >= NG) return;
    float p[64];
    #pragma unroll
    for (int f = 0; f < 64; f++) p[f] = g_pooled[g * 64 + f];
    float logits[10];
    #pragma unroll
    for (int c = 0; c < 10; c++) {
        float s = bl[c];
        #pragma unroll
        for (int f = 0; f < 64; f++) s += p[f] * Wl[f * 10 + c];
        logits[c] = s;
    }
    float m = logits[0];
    #pragma unroll
    for (int c = 1; c < 10; c++) m = fmaxf(m, logits[c]);
    float sum = 0.f;
    #pragma unroll
    for (int c = 0; c < 10; c++) { logits[c] = expf(logits[c] - m); sum += logits[c]; }
    float inv = 1.0f / sum;
    #pragma unroll
    for (int c = 0; c < 10; c++) out[g * 10 + c] = logits[c] * inv;
}

// ---------------- launch ----------------
// Inputs bound BY ELEMENT COUNT. edge_index/batch are int32 (JAX x64-disabled).

extern "C" void kernel_launch(void* const* d_in, const int* in_sizes, int n_in,
                              void* d_out, int out_size) {
    (void)out_size;
    const float* x = nullptr;
    const int* ei = nullptr;
    const int* batch = nullptr;
    const float *W1 = nullptr, *W2 = nullptr, *W3 = nullptr, *Wl = nullptr;
    const float *b1 = nullptr, *b2 = nullptr, *b3 = nullptr, *bl = nullptr;
    int ei_elems = 0, batch_elems = 0;
    int n4096 = 0, n64 = 0;

    for (int i = 0; i < n_in; i++) {
        int sz = in_sizes[i];
        const void* p = d_in[i];
        if (sz == 100000 * 128)      x = (const float*)p;
        else if (sz == 2 * 1600000)  { ei = (const int*)p; ei_elems = sz; }
        else if (sz == 100000)       { batch = (const int*)p; batch_elems = sz; }
        else if (sz == 128 * 64)     W1 = (const float*)p;
        else if (sz == 64 * 64)      { if (n4096++ == 0) W2 = (const float*)p; else W3 = (const float*)p; }
        else if (sz == 64)           { if (n64 == 0) b1 = (const float*)p;
                                       else if (n64 == 1) b2 = (const float*)p;
                                       else b3 = (const float*)p; n64++; }
        else if (sz == 64 * 10)      Wl = (const float*)p;
        else if (sz == 10)           bl = (const float*)p;
    }
    if (!x || !ei || !batch || !W1 || !W2 || !W3 || !b1 || !b2 || !b3 || !Wl || !bl)
        return;

    int n = batch_elems;     if (n > NMAX) n = NMAX;
    int E = ei_elems / 2;    if (E > EMAX) E = EMAX;

    const int TB = 256;
    const int nbN  = (n + TB - 1) / TB;
    const int nbE  = (E + TB - 1) / TB;
    const int nbGm = (n + 63) / 64;
    const int nbSc = (int)(((size_t)E * 16 + TB - 1) / TB);

    // prep: degree (with self-loop), dinv/selfw, per-edge norm
    k_init_deg<<<nbN, TB>>>(n);
    k_prep_edges<<<nbE, TB>>>(ei, E, n);
    k_dinv<<<nbN, TB>>>(n);
    k_norm<<<nbE, TB>>>(E);

    // layer 1 (K=128, input = x); gemm epilogue initializes g_agg
    k_gemm<128, false><<<nbGm, TB>>>(x, W1, b1, n);
    k_scatter<<<nbSc, TB>>>(E);

    // layer 2 (reads relu(g_agg) in-place)
    k_gemm<64, true><<<nbGm, TB>>>(nullptr, W2, b2, n);
    k_scatter<<<nbSc, TB>>>(E);

    // layer 3
    k_gemm<64, true><<<nbGm, TB>>>(nullptr, W3, b3, n);
    k_scatter<<<nbSc, TB>>>(E);

    // pool + classify
    k_pool<<<NG, TB>>>(batch, n);
    k_final<<<1, 64>>>(Wl, bl, (float*)d_out);
}